// round 7
// baseline (speedup 1.0000x reference)
#include <cuda_runtime.h>

#define S_LEN 4096
#define B_SZ  2
#define DM    512
#define HN    8
#define DH    64
#define NSPLIT 4
#define KPS   (S_LEN / NSPLIT)   // 1024 keys per split

typedef unsigned long long ull;

// ---------------- packed f32x2 helpers (PTX-only on Blackwell) ----------------
__device__ __forceinline__ void ffma2(ull& d, ull a, ull b) {
    asm("fma.rn.f32x2 %0, %1, %2, %0;" : "+l"(d) : "l"(a), "l"(b));
}
__device__ __forceinline__ void fadd2(ull& d, ull a) {
    asm("add.rn.f32x2 %0, %0, %1;" : "+l"(d) : "l"(a));
}
__device__ __forceinline__ ull pack2(float x, float y) {
    ull r; asm("mov.b64 %0, {%1, %2};" : "=l"(r) : "f"(x), "f"(y)); return r;
}
__device__ __forceinline__ void unpack2(ull v, float& x, float& y) {
    asm("mov.b64 {%0, %1}, %2;" : "=f"(x), "=f"(y) : "l"(v));
}
// granule-8 swizzle (Qs / GEMM): col -> swizzled col
__device__ __forceinline__ int swz8(int col, int salt) {
    return ((((col) >> 3) ^ (salt)) << 3) | ((col) & 7);
}

// ---------------- scratch (no cudaMalloc allowed) ----------------
__device__ float g_q[(size_t)B_SZ * S_LEN * DM];
__device__ float g_k[(size_t)B_SZ * S_LEN * DM];
__device__ float g_v[(size_t)B_SZ * S_LEN * DM];
__device__ float g_ctx[(size_t)B_SZ * S_LEN * DM];
__device__ float g_opart[(size_t)NSPLIT * B_SZ * S_LEN * DM];  // unnormalized per-split O
__device__ float g_l[NSPLIT * B_SZ * HN * S_LEN];              // per-split softmax denominators

// =====================================================================
// GEMM: C[m][n] = sum_k A[m][k]*W[n][k] + bias[n]  (unchanged from R4)
// =====================================================================
__global__ void __launch_bounds__(256) gemm_bias_kernel(
    const float* __restrict__ A, const float* __restrict__ W,
    const float* __restrict__ bias, float* __restrict__ C)
{
    __shared__ __align__(16) float As[2][32][128];
    __shared__ __align__(16) float Ws[2][32][128];

    const int tid = threadIdx.x;
    const int tx = tid & 15, ty = tid >> 4;
    const int m0 = blockIdx.x * 128;
    const int n0 = blockIdx.y * 128;

    ull acc[4][8];
    #pragma unroll
    for (int i = 0; i < 4; i++)
        #pragma unroll
        for (int j = 0; j < 8; j++) acc[i][j] = 0ull;

    #pragma unroll
    for (int it = 0; it < 4; it++) {
        int e = tid + it * 256;
        int k4 = (e & 7) << 2, r = e >> 3;
        float4 va = *reinterpret_cast<const float4*>(&A[(size_t)(m0 + r) * DM + k4]);
        float4 vw = *reinterpret_cast<const float4*>(&W[(size_t)(n0 + r) * DM + k4]);
        int c0 = swz8(r, k4 >> 2);
        As[0][k4 + 0][c0] = va.x; As[0][k4 + 1][c0] = va.y;
        As[0][k4 + 2][c0] = va.z; As[0][k4 + 3][c0] = va.w;
        Ws[0][k4 + 0][c0] = vw.x; Ws[0][k4 + 1][c0] = vw.y;
        Ws[0][k4 + 2][c0] = vw.z; Ws[0][k4 + 3][c0] = vw.w;
    }
    __syncthreads();

    const int NSLAB = DM / 32;  // 16
    #pragma unroll 1
    for (int s = 0; s < NSLAB; s++) {
        const int buf = s & 1;
        float4 ra[4], rw[4];
        if (s + 1 < NSLAB) {
            const int k0 = (s + 1) * 32;
            #pragma unroll
            for (int it = 0; it < 4; it++) {
                int e = tid + it * 256;
                int k4 = (e & 7) << 2, r = e >> 3;
                ra[it] = *reinterpret_cast<const float4*>(&A[(size_t)(m0 + r) * DM + k0 + k4]);
                rw[it] = *reinterpret_cast<const float4*>(&W[(size_t)(n0 + r) * DM + k0 + k4]);
            }
        }
        #pragma unroll 4
        for (int k = 0; k < 32; k++) {
            const int salt = k >> 2;
            const float* arow = &As[buf][k][(ty ^ salt) << 3];
            ulonglong2 a0 = *reinterpret_cast<const ulonglong2*>(arow);
            ulonglong2 a1 = *reinterpret_cast<const ulonglong2*>(arow + 4);
            const float* wrow = &Ws[buf][k][(tx ^ salt) << 3];
            float4 w0 = *reinterpret_cast<const float4*>(wrow);
            float4 w1 = *reinterpret_cast<const float4*>(wrow + 4);
            ull wd[8];
            wd[0] = pack2(w0.x, w0.x); wd[1] = pack2(w0.y, w0.y);
            wd[2] = pack2(w0.z, w0.z); wd[3] = pack2(w0.w, w0.w);
            wd[4] = pack2(w1.x, w1.x); wd[5] = pack2(w1.y, w1.y);
            wd[6] = pack2(w1.z, w1.z); wd[7] = pack2(w1.w, w1.w);
            #pragma unroll
            for (int j = 0; j < 8; j++) {
                ffma2(acc[0][j], a0.x, wd[j]);
                ffma2(acc[1][j], a0.y, wd[j]);
                ffma2(acc[2][j], a1.x, wd[j]);
                ffma2(acc[3][j], a1.y, wd[j]);
            }
        }
        if (s + 1 < NSLAB) {
            const int nb = buf ^ 1;
            #pragma unroll
            for (int it = 0; it < 4; it++) {
                int e = tid + it * 256;
                int k4 = (e & 7) << 2, r = e >> 3;
                int c0 = swz8(r, k4 >> 2);
                As[nb][k4 + 0][c0] = ra[it].x; As[nb][k4 + 1][c0] = ra[it].y;
                As[nb][k4 + 2][c0] = ra[it].z; As[nb][k4 + 3][c0] = ra[it].w;
                Ws[nb][k4 + 0][c0] = rw[it].x; Ws[nb][k4 + 1][c0] = rw[it].y;
                Ws[nb][k4 + 2][c0] = rw[it].z; Ws[nb][k4 + 3][c0] = rw[it].w;
            }
        }
        __syncthreads();
    }

    float4 b0 = *reinterpret_cast<const float4*>(&bias[n0 + tx * 8]);
    float4 b1 = *reinterpret_cast<const float4*>(&bias[n0 + tx * 8 + 4]);
    #pragma unroll
    for (int mp = 0; mp < 4; mp++) {
        float lo[8], hi[8];
        #pragma unroll
        for (int j = 0; j < 8; j++) unpack2(acc[mp][j], lo[j], hi[j]);
        size_t r0 = (size_t)(m0 + ty * 8 + 2 * mp) * DM + n0 + tx * 8;
        size_t r1 = r0 + DM;
        *reinterpret_cast<float4*>(&C[r0])     = make_float4(lo[0] + b0.x, lo[1] + b0.y, lo[2] + b0.z, lo[3] + b0.w);
        *reinterpret_cast<float4*>(&C[r0 + 4]) = make_float4(lo[4] + b1.x, lo[5] + b1.y, lo[6] + b1.z, lo[7] + b1.w);
        *reinterpret_cast<float4*>(&C[r1])     = make_float4(hi[0] + b0.x, hi[1] + b0.y, hi[2] + b0.z, hi[3] + b0.w);
        *reinterpret_cast<float4*>(&C[r1 + 4]) = make_float4(hi[4] + b1.x, hi[5] + b1.y, hi[6] + b1.z, hi[7] + b1.w);
    }
}

// =====================================================================
// Flash attention (no-max softmax), split-KV, 128q x 64k tiles, 2 CTA/SM.
// Block 256 = 16(tx) x 16(ty). QK: 8q(4 pairs) x 4 keys {4tx..4tx+3}.
// PV: 8q x 4 dv {4tx..4tx+3}, V pre-duplicated in smem (no packs in PV).
// Smem (floats, 28672 = 112 KB):
//   Qs[64][128]   [d][q], granule-8 swizzle salt=(d>>2)&15
//   Ks[64][64]    [d][k], granule-4-ish swizzle (R4 pattern)
//   Vsd[64][128]  [kv][2*dv] duplicated, granule-4 swizzle salt=kv&31
//   Ps[64][128]   [k][q] packed pairs, granule-4 swizzle salt=k>>2
// =====================================================================
#define QS_OFF 0
#define KS_OFF (64 * 128)
#define VS_OFF (KS_OFF + 64 * 64)
#define PS_OFF (VS_OFF + 64 * 128)
#define ATTN_SMEM_FLOATS (PS_OFF + 64 * 128)   // 28672 floats = 114688 B

__global__ void __launch_bounds__(256, 2) attn_kernel(
    const float* __restrict__ Q, const float* __restrict__ K,
    const float* __restrict__ V)
{
    extern __shared__ __align__(16) float sm[];
    float* Qs  = sm + QS_OFF;
    float* Ks  = sm + KS_OFF;
    float* Vsd = sm + VS_OFF;
    float* Ps  = sm + PS_OFF;

    const int tid = threadIdx.x;
    const int tx = tid & 15, ty = tid >> 4;
    const int bh = blockIdx.y;
    const int b = bh >> 3, h = bh & 7;
    const int q0 = blockIdx.x * 128;
    const int split = blockIdx.z;
    const int kbase = split * KPS;

    const float* Qb = Q + (size_t)b * S_LEN * DM + (size_t)h * DH;
    const float* Kb = K + (size_t)b * S_LEN * DM + (size_t)h * DH;
    const float* Vb = V + (size_t)b * S_LEN * DM + (size_t)h * DH;

    // ---- stage Q tile (128 q x 64 d) transposed [d][q sw8], pre-scaled ----
    #pragma unroll
    for (int it = 0; it < 8; it++) {
        int e = tid + it * 256;
        int d4 = (e & 15) << 2, qq = e >> 4;
        float4 v = *reinterpret_cast<const float4*>(&Qb[(size_t)(q0 + qq) * DM + d4]);
        int c0 = swz8(qq, (d4 >> 2) & 15);
        Qs[(d4 + 0) * 128 + c0] = v.x * 0.125f;
        Qs[(d4 + 1) * 128 + c0] = v.y * 0.125f;
        Qs[(d4 + 2) * 128 + c0] = v.z * 0.125f;
        Qs[(d4 + 3) * 128 + c0] = v.w * 0.125f;
    }

    ull O2[4][4];
    ull lacc[4];
    #pragma unroll
    for (int i = 0; i < 4; i++) {
        lacc[i] = 0ull;
        #pragma unroll
        for (int j = 0; j < 4; j++) O2[i][j] = 0ull;
    }

    #pragma unroll 1
    for (int kt = 0; kt < KPS / 64; kt++) {
        const int kk0 = kbase + kt * 64;
        __syncthreads();   // prior PV done with Ps/Vsd, prior QK done with Ks
        #pragma unroll
        for (int it = 0; it < 4; it++) {
            int e = tid + it * 256;
            int d4 = (e & 15) << 2, r = e >> 4;   // r: key 0..63
            float4 kv4 = *reinterpret_cast<const float4*>(&Kb[(size_t)(kk0 + r) * DM + d4]);
            int c0 = swz8(r, (d4 >> 2) & 7);
            Ks[(d4 + 0) * 64 + c0] = kv4.x;
            Ks[(d4 + 1) * 64 + c0] = kv4.y;
            Ks[(d4 + 2) * 64 + c0] = kv4.z;
            Ks[(d4 + 3) * 64 + c0] = kv4.w;
            // V duplicated: logical cols [2*d4 .. 2*d4+7], granules g,g+1 (g=d4>>1)
            float4 vv4 = *reinterpret_cast<const float4*>(&Vb[(size_t)(kk0 + r) * DM + d4]);
            int g = d4 >> 1;                  // even granule index
            int sv = r & 31;
            float* vrow = &Vsd[r * 128];
            *reinterpret_cast<ulonglong2*>(vrow + ((g ^ sv) << 2)) =
                make_ulonglong2(pack2(vv4.x, vv4.x), pack2(vv4.y, vv4.y));
            *reinterpret_cast<ulonglong2*>(vrow + (((g + 1) ^ sv) << 2)) =
                make_ulonglong2(pack2(vv4.z, vv4.z), pack2(vv4.w, vv4.w));
        }
        __syncthreads();

        // ---- S = Qscaled @ K^T : 4 q-pairs x 4 contiguous keys (4tx+j) ----
        ull S2[4][4];
        #pragma unroll
        for (int i = 0; i < 4; i++)
            #pragma unroll
            for (int j = 0; j < 4; j++) S2[i][j] = 0ull;

        #pragma unroll 4
        for (int d = 0; d < 64; d++) {
            const int sd = (d >> 2) & 15;
            const float* qrow = &Qs[d * 128 + ((ty ^ sd) << 3)];
            ulonglong2 qa  = *reinterpret_cast<const ulonglong2*>(qrow);
            ulonglong2 qb2 = *reinterpret_cast<const ulonglong2*>(qrow + 4);
            float4 kv4 = *reinterpret_cast<const float4*>(
                &Ks[d * 64 + ((((tx >> 1) ^ (sd & 7)) << 3) | ((tx & 1) << 2))]);
            ull kd[4];
            kd[0] = pack2(kv4.x, kv4.x); kd[1] = pack2(kv4.y, kv4.y);
            kd[2] = pack2(kv4.z, kv4.z); kd[3] = pack2(kv4.w, kv4.w);
            #pragma unroll
            for (int j = 0; j < 4; j++) {
                ffma2(S2[0][j], qa.x,  kd[j]);
                ffma2(S2[1][j], qa.y,  kd[j]);
                ffma2(S2[2][j], qb2.x, kd[j]);
                ffma2(S2[3][j], qb2.y, kd[j]);
            }
        }

        // ---- P = exp(S); write Ps[k][q-granule ^ (k>>2)] ----
        #pragma unroll
        for (int j = 0; j < 4; j++) {
            const int kj = 4 * tx + j;
            ull p[4];
            #pragma unroll
            for (int qp = 0; qp < 4; qp++) {
                float s0, s1;
                unpack2(S2[qp][j], s0, s1);
                p[qp] = pack2(__expf(s0), __expf(s1));
                fadd2(lacc[qp], p[qp]);
            }
            int p0 = (2 * ty) ^ tx;           // salt = kj>>2 = tx
            float* prow = &Ps[kj * 128];
            *reinterpret_cast<ulonglong2*>(prow + (p0 << 2))       = make_ulonglong2(p[0], p[1]);
            *reinterpret_cast<ulonglong2*>(prow + ((p0 ^ 1) << 2)) = make_ulonglong2(p[2], p[3]);
        }
        __syncthreads();

        // ---- O += P @ V : 4 q-pairs x 4 dv, V pairs direct from smem ----
        #pragma unroll 4
        for (int kv = 0; kv < 64; kv++) {
            const int sp = kv >> 2;
            int p0 = (2 * ty) ^ sp;
            const float* prow = &Ps[kv * 128];
            ulonglong2 pa = *reinterpret_cast<const ulonglong2*>(prow + (p0 << 2));
            ulonglong2 pb = *reinterpret_cast<const ulonglong2*>(prow + ((p0 ^ 1) << 2));
            const int sv = kv & 31;
            const float* vrow = &Vsd[kv * 128];
            ulonglong2 va = *reinterpret_cast<const ulonglong2*>(vrow + (((2 * tx) ^ sv) << 2));
            ulonglong2 vb = *reinterpret_cast<const ulonglong2*>(vrow + (((2 * tx + 1) ^ sv) << 2));
            ffma2(O2[0][0], pa.x, va.x); ffma2(O2[0][1], pa.x, va.y);
            ffma2(O2[0][2], pa.x, vb.x); ffma2(O2[0][3], pa.x, vb.y);
            ffma2(O2[1][0], pa.y, va.x); ffma2(O2[1][1], pa.y, va.y);
            ffma2(O2[1][2], pa.y, vb.x); ffma2(O2[1][3], pa.y, vb.y);
            ffma2(O2[2][0], pb.x, va.x); ffma2(O2[2][1], pb.x, va.y);
            ffma2(O2[2][2], pb.x, vb.x); ffma2(O2[2][3], pb.x, vb.y);
            ffma2(O2[3][0], pb.y, va.x); ffma2(O2[3][1], pb.y, va.y);
            ffma2(O2[3][2], pb.y, vb.x); ffma2(O2[3][3], pb.y, vb.y);
        }
    }

    // ---- epilogue: reduce l across 16 tx lanes, write unnormalized O + l ----
    float l[8];
    #pragma unroll
    for (int qp = 0; qp < 4; qp++) unpack2(lacc[qp], l[2 * qp], l[2 * qp + 1]);
    #pragma unroll
    for (int i = 0; i < 8; i++) {
        #pragma unroll
        for (int off = 1; off < 16; off <<= 1)
            l[i] += __shfl_xor_sync(0xffffffffu, l[i], off);
    }

    float* Ob = g_opart + ((((size_t)split * B_SZ + b) * HN + h) * S_LEN + q0) * DH;
    #pragma unroll
    for (int qp = 0; qp < 4; qp++) {
        float lo[4], hi[4];
        #pragma unroll
        for (int j = 0; j < 4; j++) unpack2(O2[qp][j], lo[j], hi[j]);
        size_t r0 = (size_t)(ty * 8 + 2 * qp) * DH + tx * 4;
        *reinterpret_cast<float4*>(&Ob[r0])      = make_float4(lo[0], lo[1], lo[2], lo[3]);
        *reinterpret_cast<float4*>(&Ob[r0 + DH]) = make_float4(hi[0], hi[1], hi[2], hi[3]);
    }
    if (tx == 0) {
        float* Lb = g_l + ((size_t)(split * B_SZ + b) * HN + h) * S_LEN + q0 + ty * 8;
        #pragma unroll
        for (int i = 0; i < 8; i++) Lb[i] = l[i];
    }
}

// =====================================================================
// Merge split-KV partials: ctx[b][q][h*64+dv] = sum_s O_s / sum_s l_s
// =====================================================================
__global__ void __launch_bounds__(256) merge_kernel()
{
    int idx = blockIdx.x * 256 + threadIdx.x;
    int dv4 = (idx & 15) << 2;
    int q   = (idx >> 4) & 4095;
    int h   = (idx >> 16) & 7;
    int b   = idx >> 19;

    float sx = 0.f, sy = 0.f, sz = 0.f, sw = 0.f, lsum = 0.f;
    #pragma unroll
    for (int s = 0; s < NSPLIT; s++) {
        size_t ob = ((((size_t)s * B_SZ + b) * HN + h) * S_LEN + q) * DH + dv4;
        float4 v = *reinterpret_cast<const float4*>(&g_opart[ob]);
        sx += v.x; sy += v.y; sz += v.z; sw += v.w;
        lsum += g_l[((size_t)(s * B_SZ + b) * HN + h) * S_LEN + q];
    }
    float inv = 1.0f / lsum;
    size_t co = ((size_t)b * S_LEN + q) * DM + h * DH + dv4;
    *reinterpret_cast<float4*>(&g_ctx[co]) = make_float4(sx * inv, sy * inv, sz * inv, sw * inv);
}

// =====================================================================
extern "C" void kernel_launch(void* const* d_in, const int* in_sizes, int n_in,
                              void* d_out, int out_size)
{
    const float* q  = (const float*)d_in[0];
    const float* k  = (const float*)d_in[1];
    const float* v  = (const float*)d_in[2];
    const float* Wq = (const float*)d_in[3];
    const float* bq = (const float*)d_in[4];
    const float* Wk = (const float*)d_in[5];
    const float* bk = (const float*)d_in[6];
    const float* Wv = (const float*)d_in[7];
    const float* bv = (const float*)d_in[8];
    const float* Wo = (const float*)d_in[9];
    const float* bo = (const float*)d_in[10];
    float* out = (float*)d_out;

    float *gq, *gk, *gv, *gctx;
    cudaGetSymbolAddress((void**)&gq, g_q);
    cudaGetSymbolAddress((void**)&gk, g_k);
    cudaGetSymbolAddress((void**)&gv, g_v);
    cudaGetSymbolAddress((void**)&gctx, g_ctx);

    const int ATTN_SMEM = ATTN_SMEM_FLOATS * 4;   // 114688 B -> 2 CTAs/SM
    cudaFuncSetAttribute(attn_kernel, cudaFuncAttributeMaxDynamicSharedMemorySize, ATTN_SMEM);

    dim3 ggrid(64, 4);   // (8192/128, 512/128)
    gemm_bias_kernel<<<ggrid, 256>>>(q, Wq, bq, gq);
    gemm_bias_kernel<<<ggrid, 256>>>(k, Wk, bk, gk);
    gemm_bias_kernel<<<ggrid, 256>>>(v, Wv, bv, gv);

    dim3 agrid(S_LEN / 128, B_SZ * HN, NSPLIT);   // (32, 16, 4)
    attn_kernel<<<agrid, 256, ATTN_SMEM>>>(gq, gk, gv);

    merge_kernel<<<(B_SZ * HN * S_LEN * (DH / 4)) / 256, 256>>>();   // 8192 blocks

    gemm_bias_kernel<<<ggrid, 256>>>(gctx, Wo, bo, out);
}

// round 8
// speedup vs baseline: 1.2866x; 1.2866x over previous
#include <cuda_runtime.h>

#define S_LEN 4096
#define B_SZ  2
#define DM    512
#define HN    8
#define DH    64
#define NSPLIT 4
#define KPS   (S_LEN / NSPLIT)   // 1024 keys per split

typedef unsigned long long ull;

// ---------------- packed f32x2 helpers (PTX-only on Blackwell) ----------------
__device__ __forceinline__ void ffma2(ull& d, ull a, ull b) {
    asm("fma.rn.f32x2 %0, %1, %2, %0;" : "+l"(d) : "l"(a), "l"(b));
}
__device__ __forceinline__ void fadd2(ull& d, ull a) {
    asm("add.rn.f32x2 %0, %0, %1;" : "+l"(d) : "l"(a));
}
__device__ __forceinline__ ull pack2(float x, float y) {
    ull r; asm("mov.b64 %0, {%1, %2};" : "=l"(r) : "f"(x), "f"(y)); return r;
}
__device__ __forceinline__ void unpack2(ull v, float& x, float& y) {
    asm("mov.b64 {%0, %1}, %2;" : "=f"(x), "=f"(y) : "l"(v));
}
// granule-8 swizzle (Qs / GEMM): col -> swizzled col
__device__ __forceinline__ int swz8(int col, int salt) {
    return ((((col) >> 3) ^ (salt)) << 3) | ((col) & 7);
}

// ---------------- scratch (no cudaMalloc allowed) ----------------
__device__ float g_q[(size_t)B_SZ * S_LEN * DM];
__device__ float g_k[(size_t)B_SZ * S_LEN * DM];
__device__ float g_v[(size_t)B_SZ * S_LEN * DM];
__device__ float g_opart[(size_t)NSPLIT * B_SZ * S_LEN * DM];  // unnormalized per-split O
__device__ float g_l[NSPLIT * B_SZ * HN * S_LEN];              // per-split softmax denominators

// merged attention output element (float4): sum_s opart / sum_s l
__device__ __forceinline__ float4 merged_A(int m, int col) {
    int b = m >> 12, q = m & 4095;
    int h = col >> 6, dv = col & 63;
    float4 acc = make_float4(0.f, 0.f, 0.f, 0.f);
    float lsum = 0.f;
    #pragma unroll
    for (int s = 0; s < NSPLIT; s++) {
        const float4 v = *reinterpret_cast<const float4*>(
            &g_opart[((((size_t)s * B_SZ + b) * HN + h) * S_LEN + q) * DH + dv]);
        acc.x += v.x; acc.y += v.y; acc.z += v.z; acc.w += v.w;
        lsum += g_l[((size_t)(s * B_SZ + b) * HN + h) * S_LEN + q];
    }
    float inv = 1.0f / lsum;
    acc.x *= inv; acc.y *= inv; acc.z *= inv; acc.w *= inv;
    return acc;
}

// =====================================================================
// GEMM: C[m][n] = sum_k A[m][k]*W[n][k] + bias[n]
// MERGE=true: A element = merged attention output (merge fused in staging).
// =====================================================================
template<bool MERGE>
__global__ void __launch_bounds__(256) gemm_bias_kernel(
    const float* __restrict__ A, const float* __restrict__ W,
    const float* __restrict__ bias, float* __restrict__ C)
{
    __shared__ __align__(16) float As[2][32][128];
    __shared__ __align__(16) float Ws[2][32][128];

    const int tid = threadIdx.x;
    const int tx = tid & 15, ty = tid >> 4;
    const int m0 = blockIdx.x * 128;
    const int n0 = blockIdx.y * 128;

    ull acc[4][8];
    #pragma unroll
    for (int i = 0; i < 4; i++)
        #pragma unroll
        for (int j = 0; j < 8; j++) acc[i][j] = 0ull;

    #pragma unroll
    for (int it = 0; it < 4; it++) {
        int e = tid + it * 256;
        int k4 = (e & 7) << 2, r = e >> 3;
        float4 va = MERGE ? merged_A(m0 + r, k4)
                          : *reinterpret_cast<const float4*>(&A[(size_t)(m0 + r) * DM + k4]);
        float4 vw = *reinterpret_cast<const float4*>(&W[(size_t)(n0 + r) * DM + k4]);
        int c0 = swz8(r, k4 >> 2);
        As[0][k4 + 0][c0] = va.x; As[0][k4 + 1][c0] = va.y;
        As[0][k4 + 2][c0] = va.z; As[0][k4 + 3][c0] = va.w;
        Ws[0][k4 + 0][c0] = vw.x; Ws[0][k4 + 1][c0] = vw.y;
        Ws[0][k4 + 2][c0] = vw.z; Ws[0][k4 + 3][c0] = vw.w;
    }
    __syncthreads();

    const int NSLAB = DM / 32;  // 16
    #pragma unroll 1
    for (int s = 0; s < NSLAB; s++) {
        const int buf = s & 1;
        float4 ra[4], rw[4];
        if (s + 1 < NSLAB) {
            const int k0 = (s + 1) * 32;
            #pragma unroll
            for (int it = 0; it < 4; it++) {
                int e = tid + it * 256;
                int k4 = (e & 7) << 2, r = e >> 3;
                ra[it] = MERGE ? merged_A(m0 + r, k0 + k4)
                               : *reinterpret_cast<const float4*>(&A[(size_t)(m0 + r) * DM + k0 + k4]);
                rw[it] = *reinterpret_cast<const float4*>(&W[(size_t)(n0 + r) * DM + k0 + k4]);
            }
        }
        #pragma unroll 4
        for (int k = 0; k < 32; k++) {
            const int salt = k >> 2;
            const float* arow = &As[buf][k][(ty ^ salt) << 3];
            ulonglong2 a0 = *reinterpret_cast<const ulonglong2*>(arow);
            ulonglong2 a1 = *reinterpret_cast<const ulonglong2*>(arow + 4);
            const float* wrow = &Ws[buf][k][(tx ^ salt) << 3];
            float4 w0 = *reinterpret_cast<const float4*>(wrow);
            float4 w1 = *reinterpret_cast<const float4*>(wrow + 4);
            ull wd[8];
            wd[0] = pack2(w0.x, w0.x); wd[1] = pack2(w0.y, w0.y);
            wd[2] = pack2(w0.z, w0.z); wd[3] = pack2(w0.w, w0.w);
            wd[4] = pack2(w1.x, w1.x); wd[5] = pack2(w1.y, w1.y);
            wd[6] = pack2(w1.z, w1.z); wd[7] = pack2(w1.w, w1.w);
            #pragma unroll
            for (int j = 0; j < 8; j++) {
                ffma2(acc[0][j], a0.x, wd[j]);
                ffma2(acc[1][j], a0.y, wd[j]);
                ffma2(acc[2][j], a1.x, wd[j]);
                ffma2(acc[3][j], a1.y, wd[j]);
            }
        }
        if (s + 1 < NSLAB) {
            const int nb = buf ^ 1;
            #pragma unroll
            for (int it = 0; it < 4; it++) {
                int e = tid + it * 256;
                int k4 = (e & 7) << 2, r = e >> 3;
                int c0 = swz8(r, k4 >> 2);
                As[nb][k4 + 0][c0] = ra[it].x; As[nb][k4 + 1][c0] = ra[it].y;
                As[nb][k4 + 2][c0] = ra[it].z; As[nb][k4 + 3][c0] = ra[it].w;
                Ws[nb][k4 + 0][c0] = rw[it].x; Ws[nb][k4 + 1][c0] = rw[it].y;
                Ws[nb][k4 + 2][c0] = rw[it].z; Ws[nb][k4 + 3][c0] = rw[it].w;
            }
        }
        __syncthreads();
    }

    float4 b0 = *reinterpret_cast<const float4*>(&bias[n0 + tx * 8]);
    float4 b1 = *reinterpret_cast<const float4*>(&bias[n0 + tx * 8 + 4]);
    #pragma unroll
    for (int mp = 0; mp < 4; mp++) {
        float lo[8], hi[8];
        #pragma unroll
        for (int j = 0; j < 8; j++) unpack2(acc[mp][j], lo[j], hi[j]);
        size_t r0 = (size_t)(m0 + ty * 8 + 2 * mp) * DM + n0 + tx * 8;
        size_t r1 = r0 + DM;
        *reinterpret_cast<float4*>(&C[r0])     = make_float4(lo[0] + b0.x, lo[1] + b0.y, lo[2] + b0.z, lo[3] + b0.w);
        *reinterpret_cast<float4*>(&C[r0 + 4]) = make_float4(lo[4] + b1.x, lo[5] + b1.y, lo[6] + b1.z, lo[7] + b1.w);
        *reinterpret_cast<float4*>(&C[r1])     = make_float4(hi[0] + b0.x, hi[1] + b0.y, hi[2] + b0.z, hi[3] + b0.w);
        *reinterpret_cast<float4*>(&C[r1 + 4]) = make_float4(hi[4] + b1.x, hi[5] + b1.y, hi[6] + b1.z, hi[7] + b1.w);
    }
}

// =====================================================================
// Flash attention (no-max softmax), split-KV, 128q x 64k tiles, 2 CTA/SM.
// Block 256 = 16(tx) x 16(ty). QK: 8q(4 pairs) x 4 keys {tx+16j}.
// PV: 8q x 4 dv {4tx..4tx+3}.
// Smem (floats, 24832 = 97 KB):
//   Qs[64][128]  [d][q], granule-8 swizzle salt=(d>>2)&15
//   Ks[64 keys][stride 68]  [key][d]  (odd quad stride -> conflict-free both ways)
//   Vs[64][64]   [kv][dv]
//   Ps[64][128]  [k][q pairs], granule-4 swizzle salt=k&15
// =====================================================================
#define QS_OFF 0
#define KS_OFF (64 * 128)
#define VS_OFF (KS_OFF + 64 * 68)
#define PS_OFF (VS_OFF + 64 * 64)
#define ATTN_SMEM_FLOATS (PS_OFF + 64 * 128)   // 24832 floats = 99328 B

__global__ void __launch_bounds__(256, 2) attn_kernel(
    const float* __restrict__ Q, const float* __restrict__ K,
    const float* __restrict__ V)
{
    extern __shared__ __align__(16) float sm[];
    float* Qs = sm + QS_OFF;
    float* Ks = sm + KS_OFF;
    float* Vs = sm + VS_OFF;
    float* Ps = sm + PS_OFF;

    const int tid = threadIdx.x;
    const int tx = tid & 15, ty = tid >> 4;
    const int bh = blockIdx.y;
    const int b = bh >> 3, h = bh & 7;
    const int q0 = blockIdx.x * 128;
    const int split = blockIdx.z;
    const int kbase = split * KPS;

    const float* Qb = Q + (size_t)b * S_LEN * DM + (size_t)h * DH;
    const float* Kb = K + (size_t)b * S_LEN * DM + (size_t)h * DH;
    const float* Vb = V + (size_t)b * S_LEN * DM + (size_t)h * DH;

    // ---- stage Q tile (128 q x 64 d) transposed [d][q sw8], pre-scaled ----
    #pragma unroll
    for (int it = 0; it < 8; it++) {
        int e = tid + it * 256;
        int d4 = (e & 15) << 2, qq = e >> 4;
        float4 v = *reinterpret_cast<const float4*>(&Qb[(size_t)(q0 + qq) * DM + d4]);
        int c0 = swz8(qq, (d4 >> 2) & 15);
        Qs[(d4 + 0) * 128 + c0] = v.x * 0.125f;
        Qs[(d4 + 1) * 128 + c0] = v.y * 0.125f;
        Qs[(d4 + 2) * 128 + c0] = v.z * 0.125f;
        Qs[(d4 + 3) * 128 + c0] = v.w * 0.125f;
    }

    ull O2[4][4];
    ull lacc[4];
    #pragma unroll
    for (int i = 0; i < 4; i++) {
        lacc[i] = 0ull;
        #pragma unroll
        for (int j = 0; j < 4; j++) O2[i][j] = 0ull;
    }

    const int ps_g = (2 * ty) ^ tx;   // Ps store granule (salt = kj&15 = tx)

    #pragma unroll 1
    for (int kt = 0; kt < KPS / 64; kt++) {
        const int kk0 = kbase + kt * 64;
        __syncthreads();   // prior PV done with Ps/Vs, prior QK done with Ks
        // ---- stage K [key][d, stride 68] and V [kv][dv] : plain STS.128 ----
        #pragma unroll
        for (int it = 0; it < 4; it++) {
            int e = tid + it * 256;
            int d4 = (e & 15) << 2, r = e >> 4;   // r: key 0..63
            float4 kv4 = *reinterpret_cast<const float4*>(&Kb[(size_t)(kk0 + r) * DM + d4]);
            *reinterpret_cast<float4*>(&Ks[r * 68 + d4]) = kv4;
            float4 vv4 = *reinterpret_cast<const float4*>(&Vb[(size_t)(kk0 + r) * DM + d4]);
            *reinterpret_cast<float4*>(&Vs[r * 64 + d4]) = vv4;
        }
        __syncthreads();

        // ---- S = Qscaled @ K^T : 4 q-pairs x 4 keys (kj = tx + 16j) ----
        ull S2[4][4];
        #pragma unroll
        for (int i = 0; i < 4; i++)
            #pragma unroll
            for (int j = 0; j < 4; j++) S2[i][j] = 0ull;

        #pragma unroll 2
        for (int d4 = 0; d4 < 64; d4 += 4) {
            float kr[4][4];
            #pragma unroll
            for (int j = 0; j < 4; j++)
                *reinterpret_cast<float4*>(kr[j]) =
                    *reinterpret_cast<const float4*>(&Ks[(tx + 16 * j) * 68 + d4]);
            const float* qbase = &Qs[d4 * 128 + ((ty ^ ((d4 >> 2) & 15)) << 3)];
            #pragma unroll
            for (int dd = 0; dd < 3 + 1; dd++) {
                ulonglong2 qa  = *reinterpret_cast<const ulonglong2*>(qbase + dd * 128);
                ulonglong2 qb2 = *reinterpret_cast<const ulonglong2*>(qbase + dd * 128 + 4);
                ull kd0 = pack2(kr[0][dd], kr[0][dd]);
                ull kd1 = pack2(kr[1][dd], kr[1][dd]);
                ull kd2 = pack2(kr[2][dd], kr[2][dd]);
                ull kd3 = pack2(kr[3][dd], kr[3][dd]);
                ffma2(S2[0][0], qa.x,  kd0); ffma2(S2[0][1], qa.x,  kd1);
                ffma2(S2[0][2], qa.x,  kd2); ffma2(S2[0][3], qa.x,  kd3);
                ffma2(S2[1][0], qa.y,  kd0); ffma2(S2[1][1], qa.y,  kd1);
                ffma2(S2[1][2], qa.y,  kd2); ffma2(S2[1][3], qa.y,  kd3);
                ffma2(S2[2][0], qb2.x, kd0); ffma2(S2[2][1], qb2.x, kd1);
                ffma2(S2[2][2], qb2.x, kd2); ffma2(S2[2][3], qb2.x, kd3);
                ffma2(S2[3][0], qb2.y, kd0); ffma2(S2[3][1], qb2.y, kd1);
                ffma2(S2[3][2], qb2.y, kd2); ffma2(S2[3][3], qb2.y, kd3);
            }
        }

        // ---- P = exp(S); write Ps[kj][q granule ^ (kj&15)] ----
        #pragma unroll
        for (int j = 0; j < 4; j++) {
            const int kj = tx + 16 * j;
            ull p[4];
            #pragma unroll
            for (int qp = 0; qp < 4; qp++) {
                float s0, s1;
                unpack2(S2[qp][j], s0, s1);
                p[qp] = pack2(__expf(s0), __expf(s1));
                fadd2(lacc[qp], p[qp]);
            }
            float* prow = &Ps[kj * 128];
            *reinterpret_cast<ulonglong2*>(prow + (ps_g << 2))       = make_ulonglong2(p[0], p[1]);
            *reinterpret_cast<ulonglong2*>(prow + ((ps_g ^ 1) << 2)) = make_ulonglong2(p[2], p[3]);
        }
        __syncthreads();

        // ---- O += P @ V : 4 q-pairs x 4 dv (4tx..4tx+3) ----
        #pragma unroll 4
        for (int kv = 0; kv < 64; kv++) {
            int p0 = (2 * ty) ^ (kv & 15);
            const float* prow = &Ps[kv * 128];
            ulonglong2 pa = *reinterpret_cast<const ulonglong2*>(prow + (p0 << 2));
            ulonglong2 pb = *reinterpret_cast<const ulonglong2*>(prow + ((p0 ^ 1) << 2));
            float4 vv = *reinterpret_cast<const float4*>(&Vs[kv * 64 + tx * 4]);
            ull vd[4];
            vd[0] = pack2(vv.x, vv.x); vd[1] = pack2(vv.y, vv.y);
            vd[2] = pack2(vv.z, vv.z); vd[3] = pack2(vv.w, vv.w);
            #pragma unroll
            for (int j = 0; j < 4; j++) {
                ffma2(O2[0][j], pa.x, vd[j]);
                ffma2(O2[1][j], pa.y, vd[j]);
                ffma2(O2[2][j], pb.x, vd[j]);
                ffma2(O2[3][j], pb.y, vd[j]);
            }
        }
    }

    // ---- epilogue: reduce l across 16 tx lanes, write unnormalized O + l ----
    float l[8];
    #pragma unroll
    for (int qp = 0; qp < 4; qp++) unpack2(lacc[qp], l[2 * qp], l[2 * qp + 1]);
    #pragma unroll
    for (int i = 0; i < 8; i++) {
        #pragma unroll
        for (int off = 1; off < 16; off <<= 1)
            l[i] += __shfl_xor_sync(0xffffffffu, l[i], off);
    }

    float* Ob = g_opart + ((((size_t)split * B_SZ + b) * HN + h) * S_LEN + q0) * DH;
    #pragma unroll
    for (int qp = 0; qp < 4; qp++) {
        float lo[4], hi[4];
        #pragma unroll
        for (int j = 0; j < 4; j++) unpack2(O2[qp][j], lo[j], hi[j]);
        size_t r0 = (size_t)(ty * 8 + 2 * qp) * DH + tx * 4;
        *reinterpret_cast<float4*>(&Ob[r0])      = make_float4(lo[0], lo[1], lo[2], lo[3]);
        *reinterpret_cast<float4*>(&Ob[r0 + DH]) = make_float4(hi[0], hi[1], hi[2], hi[3]);
    }
    if (tx == 0) {
        float* Lb = g_l + ((size_t)(split * B_SZ + b) * HN + h) * S_LEN + q0 + ty * 8;
        #pragma unroll
        for (int i = 0; i < 8; i++) Lb[i] = l[i];
    }
}

// =====================================================================
extern "C" void kernel_launch(void* const* d_in, const int* in_sizes, int n_in,
                              void* d_out, int out_size)
{
    const float* q  = (const float*)d_in[0];
    const float* k  = (const float*)d_in[1];
    const float* v  = (const float*)d_in[2];
    const float* Wq = (const float*)d_in[3];
    const float* bq = (const float*)d_in[4];
    const float* Wk = (const float*)d_in[5];
    const float* bk = (const float*)d_in[6];
    const float* Wv = (const float*)d_in[7];
    const float* bv = (const float*)d_in[8];
    const float* Wo = (const float*)d_in[9];
    const float* bo = (const float*)d_in[10];
    float* out = (float*)d_out;

    float *gq, *gk, *gv;
    cudaGetSymbolAddress((void**)&gq, g_q);
    cudaGetSymbolAddress((void**)&gk, g_k);
    cudaGetSymbolAddress((void**)&gv, g_v);

    const int ATTN_SMEM = ATTN_SMEM_FLOATS * 4;   // 99328 B -> 2 CTAs/SM
    cudaFuncSetAttribute(attn_kernel, cudaFuncAttributeMaxDynamicSharedMemorySize, ATTN_SMEM);

    dim3 ggrid(64, 4);   // (8192/128, 512/128)
    gemm_bias_kernel<false><<<ggrid, 256>>>(q, Wq, bq, gq);
    gemm_bias_kernel<false><<<ggrid, 256>>>(k, Wk, bk, gk);
    gemm_bias_kernel<false><<<ggrid, 256>>>(v, Wv, bv, gv);

    dim3 agrid(S_LEN / 128, B_SZ * HN, NSPLIT);   // (32, 16, 4)
    attn_kernel<<<agrid, 256, ATTN_SMEM>>>(gq, gk, gv);

    // O projection with split-KV merge fused into A staging
    gemm_bias_kernel<true><<<ggrid, 256>>>(gq /*unused*/, Wo, bo, out);
}